// round 1
// baseline (speedup 1.0000x reference)
#include <cuda_runtime.h>
#include <math.h>
#include <stdint.h>

// ---------------------------------------------------------------------------
// ScaleCausalAttention: B=64, N=341, D=768, H=12, hd=64
//   qkv = x @ qkv_w^T + qkv_b        -> split/scatter to Q,K,V [B,H,N,hd]
//   attn = softmax(q k^T * 0.125 + scale-causal mask) @ v  -> AO [B*N, D]
//   out = AO @ proj_w^T + proj_b
// ---------------------------------------------------------------------------

#define BATCH 64
#define NTOK 341
#define DMODEL 768
#define NHEAD 12
#define HD 64
#define ROWS (BATCH * NTOK)      // 21824
#define QKVC (3 * DMODEL)        // 2304

// Scratch (no allocations allowed -> __device__ globals)
__device__ float g_Q[(size_t)BATCH * NHEAD * NTOK * HD];
__device__ float g_K[(size_t)BATCH * NHEAD * NTOK * HD];
__device__ float g_V[(size_t)BATCH * NHEAD * NTOK * HD];
__device__ float g_AO[(size_t)ROWS * DMODEL];

#define NEG_INF (-1e30f)

// Per-query-row allowed key prefix length, from the scale-causal mask.
// cum = {0,1,5,21,85,341}; row 0 (CLS) attends to everything.
__device__ __forceinline__ int rowlimit(int r) {
    if (r == 0)  return NTOK;
    if (r < 5)   return 5;
    if (r < 21)  return 21;
    if (r < 85)  return 85;
    return NTOK;
}

// ---------------------------------------------------------------------------
// SGEMM (TN): C[M,Ncols] = A[M,K] @ W[Ncols,K]^T + bias
// MODE 0: scatter epilogue into g_Q/g_K/g_V  (A = x, Ncols = 2304)
// MODE 1: plain epilogue to C, A comes from g_AO (Ncols = 768)
// BM=BN=128, BK=16, 256 threads, 8x8 per-thread microtile.
// ---------------------------------------------------------------------------
#define BM 128
#define BN 128
#define BK 16

template <int MODE>
__global__ void __launch_bounds__(256)
sgemm_tn(const float* __restrict__ A, const float* __restrict__ W,
         const float* __restrict__ bias, float* __restrict__ C,
         int M, int Ncols, int Kdim)
{
    __shared__ float As[BK][BM];
    __shared__ float Bs[BK][BN];

    const int t  = threadIdx.x;
    const int bm = blockIdx.y;
    const int bn = blockIdx.x;
    const int ty = t >> 4;      // 0..15
    const int tx = t & 15;      // 0..15

    const float* Aptr = (MODE == 1) ? g_AO : A;

    float acc[8][8];
#pragma unroll
    for (int i = 0; i < 8; i++)
#pragma unroll
        for (int j = 0; j < 8; j++) acc[i][j] = 0.0f;

    const int aRowBase = bm * BM;
    const int bRowBase = bn * BN;

    for (int k0 = 0; k0 < Kdim; k0 += BK) {
        // Load tiles (each thread: 2 float4 of A, 2 float4 of W), store transposed.
#pragma unroll
        for (int i = 0; i < 2; i++) {
            int idx = t * 2 + i;          // 0..511
            int row = idx >> 2;           // 0..127
            int c4  = idx & 3;            // 0..3

            int ar = aRowBase + row;
            float4 av = make_float4(0.f, 0.f, 0.f, 0.f);
            if (ar < M)
                av = *(const float4*)&Aptr[(size_t)ar * Kdim + k0 + c4 * 4];
            As[c4 * 4 + 0][row] = av.x;
            As[c4 * 4 + 1][row] = av.y;
            As[c4 * 4 + 2][row] = av.z;
            As[c4 * 4 + 3][row] = av.w;

            int br = bRowBase + row;      // Ncols is a multiple of 128 -> in range
            float4 bv = *(const float4*)&W[(size_t)br * Kdim + k0 + c4 * 4];
            Bs[c4 * 4 + 0][row] = bv.x;
            Bs[c4 * 4 + 1][row] = bv.y;
            Bs[c4 * 4 + 2][row] = bv.z;
            Bs[c4 * 4 + 3][row] = bv.w;
        }
        __syncthreads();

#pragma unroll
        for (int kk = 0; kk < BK; kk++) {
            float4 a0 = *(float4*)&As[kk][ty * 8];
            float4 a1 = *(float4*)&As[kk][ty * 8 + 4];
            float4 b0 = *(float4*)&Bs[kk][tx * 8];
            float4 b1 = *(float4*)&Bs[kk][tx * 8 + 4];
            float ar_[8] = {a0.x, a0.y, a0.z, a0.w, a1.x, a1.y, a1.z, a1.w};
            float br_[8] = {b0.x, b0.y, b0.z, b0.w, b1.x, b1.y, b1.z, b1.w};
#pragma unroll
            for (int i = 0; i < 8; i++)
#pragma unroll
                for (int j = 0; j < 8; j++)
                    acc[i][j] += ar_[i] * br_[j];
        }
        __syncthreads();
    }

    if (MODE == 0) {
        // Scatter qkv columns into Q/K/V [B,H,N,hd]
        float  bv[8];
        float* dstp[8];
        size_t off0[8];
#pragma unroll
        for (int j = 0; j < 8; j++) {
            int e = bn * BN + tx * 8 + j;
            bv[j] = bias[e];
            int which = e / DMODEL;                // 0=q,1=k,2=v
            int r = e - which * DMODEL;
            int hh = r >> 6;
            int dd = r & 63;
            dstp[j] = (which == 0) ? g_Q : (which == 1) ? g_K : g_V;
            off0[j] = (size_t)hh * NTOK * HD + dd;
        }
#pragma unroll
        for (int i = 0; i < 8; i++) {
            int row = bm * BM + ty * 8 + i;
            if (row < M) {
                int b_ = row / NTOK;
                int n_ = row - b_ * NTOK;
                size_t base = ((size_t)b_ * NHEAD) * NTOK * HD + (size_t)n_ * HD;
#pragma unroll
                for (int j = 0; j < 8; j++)
                    dstp[j][base + off0[j]] = acc[i][j] + bv[j];
            }
        }
    } else {
        int col = bn * BN + tx * 8;
        float bv[8];
#pragma unroll
        for (int j = 0; j < 8; j++) bv[j] = bias[col + j];
#pragma unroll
        for (int i = 0; i < 8; i++) {
            int row = bm * BM + ty * 8 + i;
            if (row < M) {
                float* dst = &C[(size_t)row * Ncols + col];
#pragma unroll
                for (int j = 0; j < 8; j++) dst[j] = acc[i][j] + bv[j];
            }
        }
    }
}

// ---------------------------------------------------------------------------
// Flash-style attention. grid = (B*H, 11), 256 threads.
// Each block: one (b,h) and a 32-row query tile. KC=32 key chunks,
// online softmax, per-row key-limit masking. Writes AO [B*N, D].
// ---------------------------------------------------------------------------
#define QT 32
#define KC 32

__global__ void __launch_bounds__(256)
attn_kernel()
{
    const int bh = blockIdx.x;           // 0..767
    const int qt = blockIdx.y;           // 0..10
    const int b  = bh / NHEAD;
    const int h  = bh - b * NHEAD;

    const float* Qg = g_Q + (size_t)bh * NTOK * HD;
    const float* Kg = g_K + (size_t)bh * NTOK * HD;
    const float* Vg = g_V + (size_t)bh * NTOK * HD;

    const int r0 = qt * QT;
    const int t  = threadIdx.x;

    __shared__ float Qs[QT][HD];
    __shared__ float Ks[KC][HD + 1];
    __shared__ float Vs[KC][HD];
    __shared__ float Ss[QT][KC + 1];
    __shared__ float sm[QT], sl[QT], sal[QT];

    // Load Q tile (zeros beyond valid rows)
    for (int i = t; i < QT * (HD / 4); i += 256) {
        int row = i >> 4;
        int c4  = i & 15;
        float4 v = make_float4(0.f, 0.f, 0.f, 0.f);
        if (r0 + row < NTOK)
            v = *(const float4*)&Qg[(size_t)(r0 + row) * HD + c4 * 4];
        *(float4*)&Qs[row][c4 * 4] = v;
    }
    if (t < QT) { sm[t] = NEG_INF; sl[t] = 0.0f; }

    float o[8];
#pragma unroll
    for (int i = 0; i < 8; i++) o[i] = 0.0f;
    const int qr_o = t >> 3;             // 0..31
    const int db   = (t & 7) * 8;        // 0..56

    // Max key limit in this tile (limits are nondecreasing for rows>=1;
    // tile 0 contains the CLS row which attends to all 341 keys).
    int lastRow = min(r0 + QT - 1, NTOK - 1);
    int Lmax = rowlimit(lastRow);
    if (r0 == 0) Lmax = NTOK;
    const int nchunks = (Lmax + KC - 1) / KC;

    const int kc2 = (t & 15) << 1;       // 0,2,..,30
    const int qr2 = (t >> 4) << 1;       // 0,2,..,30
    const int rowA = r0 + qr2;
    const int rowB = rowA + 1;
    const int La = rowlimit(min(rowA, NTOK - 1));
    const int Lb = rowlimit(min(rowB, NTOK - 1));
    const float sc = 0.125f;             // hd^-0.5

    for (int ch = 0; ch < nchunks; ch++) {
        const int k0 = ch * KC;
        __syncthreads();                 // protect smem reuse (and Qs on first iter)

        // Load K,V chunk (zeros beyond N)
        for (int i = t; i < KC * (HD / 4); i += 256) {
            int row = i >> 4;
            int c4  = i & 15;
            int kg  = k0 + row;
            float4 kv = make_float4(0.f, 0.f, 0.f, 0.f);
            float4 vv = make_float4(0.f, 0.f, 0.f, 0.f);
            if (kg < NTOK) {
                kv = *(const float4*)&Kg[(size_t)kg * HD + c4 * 4];
                vv = *(const float4*)&Vg[(size_t)kg * HD + c4 * 4];
            }
            Ks[row][c4 * 4 + 0] = kv.x;
            Ks[row][c4 * 4 + 1] = kv.y;
            Ks[row][c4 * 4 + 2] = kv.z;
            Ks[row][c4 * 4 + 3] = kv.w;
            *(float4*)&Vs[row][c4 * 4] = vv;
        }
        __syncthreads();

        // Scores: each thread computes a 2x2 (qr, kc) microtile
        float s00 = 0.f, s01 = 0.f, s10 = 0.f, s11 = 0.f;
#pragma unroll
        for (int d = 0; d < HD; d++) {
            float ka = Ks[kc2][d];
            float kb = Ks[kc2 + 1][d];
            float qa = Qs[qr2][d];
            float qb = Qs[qr2 + 1][d];
            s00 += qa * ka; s01 += qa * kb;
            s10 += qb * ka; s11 += qb * kb;
        }
        int ka_g = k0 + kc2, kb_g = k0 + kc2 + 1;
        Ss[qr2][kc2]         = (ka_g < La) ? s00 * sc : NEG_INF;
        Ss[qr2][kc2 + 1]     = (kb_g < La) ? s01 * sc : NEG_INF;
        Ss[qr2 + 1][kc2]     = (ka_g < Lb) ? s10 * sc : NEG_INF;
        Ss[qr2 + 1][kc2 + 1] = (kb_g < Lb) ? s11 * sc : NEG_INF;
        __syncthreads();

        // Online softmax update (one thread per row)
        if (t < QT) {
            float mo = sm[t];
            float cm = NEG_INF;
#pragma unroll
            for (int kc = 0; kc < KC; kc++) cm = fmaxf(cm, Ss[t][kc]);
            float mn = fmaxf(mo, cm);
            float a  = __expf(mo - mn);
            float sum = 0.f;
#pragma unroll
            for (int kc = 0; kc < KC; kc++) {
                float p = __expf(Ss[t][kc] - mn);
                Ss[t][kc] = p;
                sum += p;
            }
            sm[t]  = mn;
            sl[t]  = sl[t] * a + sum;
            sal[t] = a;
        }
        __syncthreads();

        // O update: thread owns (qr_o, db..db+7)
        float a = sal[qr_o];
#pragma unroll
        for (int i = 0; i < 8; i++) o[i] *= a;
#pragma unroll
        for (int kc = 0; kc < KC; kc++) {
            float p = Ss[qr_o][kc];
            float4 v0 = *(float4*)&Vs[kc][db];
            float4 v1 = *(float4*)&Vs[kc][db + 4];
            o[0] += p * v0.x; o[1] += p * v0.y;
            o[2] += p * v0.z; o[3] += p * v0.w;
            o[4] += p * v1.x; o[5] += p * v1.y;
            o[6] += p * v1.z; o[7] += p * v1.w;
        }
    }

    // Write AO [B*N, D] at column h*64 + db
    const int n = r0 + qr_o;
    if (n < NTOK) {
        float inv = 1.0f / sl[qr_o];
        float* dst = g_AO + (size_t)(b * NTOK + n) * DMODEL + h * HD + db;
#pragma unroll
        for (int i = 0; i < 8; i++) dst[i] = o[i] * inv;
    }
}

// ---------------------------------------------------------------------------
extern "C" void kernel_launch(void* const* d_in, const int* in_sizes, int n_in,
                              void* d_out, int out_size)
{
    const float* x      = (const float*)d_in[0];
    const float* qkv_w  = (const float*)d_in[1];
    const float* qkv_b  = (const float*)d_in[2];
    const float* proj_w = (const float*)d_in[3];
    const float* proj_b = (const float*)d_in[4];
    float* out = (float*)d_out;

    (void)in_sizes; (void)n_in; (void)out_size;

    // 1) QKV GEMM + scatter into g_Q/g_K/g_V
    {
        dim3 grid(QKVC / BN, (ROWS + BM - 1) / BM);   // 18 x 171
        sgemm_tn<0><<<grid, 256>>>(x, qkv_w, qkv_b, nullptr, ROWS, QKVC, DMODEL);
    }
    // 2) Attention -> g_AO
    {
        dim3 grid(BATCH * NHEAD, (NTOK + QT - 1) / QT);  // 768 x 11
        attn_kernel<<<grid, 256>>>();
    }
    // 3) Output projection
    {
        dim3 grid(DMODEL / BN, (ROWS + BM - 1) / BM);  // 6 x 171
        sgemm_tn<1><<<grid, 256>>>(nullptr, proj_w, proj_b, out, ROWS, DMODEL, DMODEL);
    }
}

// round 4
// speedup vs baseline: 1.6499x; 1.6499x over previous
#include <cuda_runtime.h>
#include <math.h>
#include <stdint.h>

// ---------------------------------------------------------------------------
// ScaleCausalAttention: B=64, N=341, D=768, H=12, hd=64
//   qkv = x @ qkv_w^T + qkv_b   -> scatter Q,K,V [B,H,N,hd]   (tf32 mma.sync)
//   attn = softmax(qk^T*0.125 + scale-causal mask) @ v -> AO  (fp32 SIMT)
//   out = AO @ proj_w^T + proj_b                              (tf32 mma.sync)
// NOTE: harness compiles via compute_100 (non-'a') PTX -> tcgen05 unavailable;
// mma.sync / cp.async (sm_80 baseline) are the fastest legal path.
// ---------------------------------------------------------------------------

#define BATCH 64
#define NTOK 341
#define DMODEL 768
#define NHEAD 12
#define HD 64
#define ROWS (BATCH * NTOK)      // 21824
#define QKVC (3 * DMODEL)        // 2304
#define KDIM 768

__device__ float g_Q[(size_t)BATCH * NHEAD * NTOK * HD];
__device__ float g_K[(size_t)BATCH * NHEAD * NTOK * HD];
__device__ float g_V[(size_t)BATCH * NHEAD * NTOK * HD];
__device__ float g_AO[(size_t)ROWS * DMODEL];

#define NEG_INF (-1e30f)

__device__ __forceinline__ int rowlimit(int r) {
    if (r == 0)  return NTOK;
    if (r < 5)   return 5;
    if (r < 21)  return 21;
    if (r < 85)  return 85;
    return NTOK;
}

// ======================= helpers =============================
__device__ __forceinline__ uint32_t smem_to_u32(const void* p) {
    uint32_t a;
    asm("{ .reg .u64 t; cvta.to.shared.u64 t, %1; cvt.u32.u64 %0, t; }" : "=r"(a) : "l"(p));
    return a;
}
__device__ __forceinline__ uint32_t tf32b(float x) {
    uint32_t u;
    asm("cvt.rna.tf32.f32 %0, %1;" : "=r"(u) : "f"(x));
    return u;
}
__device__ __forceinline__ void cp_async16(uint32_t dst, const void* src, int src_bytes) {
    asm volatile("cp.async.ca.shared.global [%0], [%1], 16, %2;"
                 :: "r"(dst), "l"(src), "r"(src_bytes) : "memory");
}
#define CP_COMMIT() asm volatile("cp.async.commit_group;" ::: "memory")
#define CP_WAIT1()  asm volatile("cp.async.wait_group 1;" ::: "memory")
#define CP_WAIT0()  asm volatile("cp.async.wait_group 0;" ::: "memory")

__device__ __forceinline__ void mma_tf32(float* d, const uint32_t* a, const uint32_t* b) {
    asm volatile(
        "mma.sync.aligned.m16n8k8.row.col.f32.tf32.tf32.f32 "
        "{%0,%1,%2,%3}, {%4,%5,%6,%7}, {%8,%9}, {%0,%1,%2,%3};"
        : "+f"(d[0]), "+f"(d[1]), "+f"(d[2]), "+f"(d[3])
        : "r"(a[0]), "r"(a[1]), "r"(a[2]), "r"(a[3]), "r"(b[0]), "r"(b[1]));
}

// ---------------------------------------------------------------------------
// tf32 mma.sync GEMM (TN): C[M,Ncols] = A[M,768] @ W[Ncols,768]^T + bias
// Block 128x128, BK=16, 128 threads (4 warps 2x2, warp tile 64x64),
// 2-stage cp.async pipeline.
// MODE 0: scatter -> g_Q/g_K/g_V ;  MODE 1: plain -> C
// ---------------------------------------------------------------------------
#define BK 16
#define SPAD 4
#define SSTRIDE (BK + SPAD)      // 20 floats

template <int MODE>
__global__ void __launch_bounds__(128)
gemm_mma(const float* __restrict__ A, const float* __restrict__ W,
         const float* __restrict__ bias, float* __restrict__ C, int M)
{
    __shared__ float As[2][128][SSTRIDE];
    __shared__ float Ws[2][128][SSTRIDE];

    const int t    = threadIdx.x;
    const int wid  = t >> 5;
    const int lane = t & 31;
    const int g    = lane >> 2;   // groupID 0..7
    const int tg   = lane & 3;    // thread-in-group 0..3
    const int wm   = wid >> 1;    // 0..1
    const int wn   = wid & 1;     // 0..1
    const int bn   = blockIdx.x;
    const int bm   = blockIdx.y;

    const float* Asrc = (MODE == 1) ? g_AO : A;
    const int aRow0 = bm * 128;
    const int bRow0 = bn * 128;

    float acc[4][8][4];
#pragma unroll
    for (int i = 0; i < 4; i++)
#pragma unroll
        for (int j = 0; j < 8; j++)
#pragma unroll
            for (int r = 0; r < 4; r++) acc[i][j][r] = 0.0f;

    const uint32_t AsAddr = smem_to_u32(&As[0][0][0]);
    const uint32_t WsAddr = smem_to_u32(&Ws[0][0][0]);
    const uint32_t stageBytes = 128 * SSTRIDE * 4;

    // Issue loads for a stage: 128 rows x 4 16B-chunks per matrix; 128 threads
    // -> 4 chunks of A and 4 of W per thread.
    auto load_stage = [&](int st, int k0) {
#pragma unroll
        for (int i = 0; i < 4; i++) {
            int cid = t + i * 128;           // 0..511
            int row = cid >> 2;
            int c4  = cid & 3;
            // A
            int gr = aRow0 + row;
            int ok = (gr < M) ? 16 : 0;
            const float* srcA = Asrc + (size_t)(ok ? gr : 0) * KDIM + k0 + c4 * 4;
            uint32_t dstA = AsAddr + st * stageBytes + (row * SSTRIDE + c4 * 4) * 4;
            cp_async16(dstA, srcA, ok);
            // W (rows always in range)
            const float* srcW = W + (size_t)(bRow0 + row) * KDIM + k0 + c4 * 4;
            uint32_t dstW = WsAddr + st * stageBytes + (row * SSTRIDE + c4 * 4) * 4;
            cp_async16(dstW, srcW, 16);
        }
        CP_COMMIT();
    };

    load_stage(0, 0);

    const int nk = KDIM / BK;   // 48
    for (int kt = 0; kt < nk; kt++) {
        if (kt + 1 < nk) load_stage((kt + 1) & 1, (kt + 1) * BK);
        if (kt + 1 < nk) CP_WAIT1(); else CP_WAIT0();
        __syncthreads();

        const int st = kt & 1;
#pragma unroll
        for (int ks = 0; ks < BK; ks += 8) {
            uint32_t afr[4][4];
#pragma unroll
            for (int mi = 0; mi < 4; mi++) {
                int r = wm * 64 + mi * 16 + g;
                afr[mi][0] = tf32b(As[st][r][ks + tg]);
                afr[mi][1] = tf32b(As[st][r + 8][ks + tg]);
                afr[mi][2] = tf32b(As[st][r][ks + tg + 4]);
                afr[mi][3] = tf32b(As[st][r + 8][ks + tg + 4]);
            }
            uint32_t bfr[8][2];
#pragma unroll
            for (int nj = 0; nj < 8; nj++) {
                int nr = wn * 64 + nj * 8 + g;
                bfr[nj][0] = tf32b(Ws[st][nr][ks + tg]);
                bfr[nj][1] = tf32b(Ws[st][nr][ks + tg + 4]);
            }
#pragma unroll
            for (int mi = 0; mi < 4; mi++)
#pragma unroll
                for (int nj = 0; nj < 8; nj++)
                    mma_tf32(acc[mi][nj], afr[mi], bfr[nj]);
        }
        __syncthreads();
    }

    // ---------------- epilogue ----------------
    const int e_base = bn * 128;
    const int which  = (MODE == 0) ? (e_base / DMODEL) : 0;
    float* dstM = (which == 0) ? g_Q : (which == 1) ? g_K : g_V;

#pragma unroll
    for (int mi = 0; mi < 4; mi++) {
#pragma unroll
        for (int half = 0; half < 2; half++) {
            int row = aRow0 + wm * 64 + mi * 16 + g + half * 8;
            if (row >= M) continue;
            int b_ = 0, n_ = 0;
            if (MODE == 0) { b_ = row / NTOK; n_ = row - b_ * NTOK; }
#pragma unroll
            for (int nj = 0; nj < 8; nj++) {
                int ncol = wn * 64 + nj * 8 + tg * 2;   // even
                int e = e_base + ncol;
                float v0 = acc[mi][nj][half * 2 + 0] + bias[e];
                float v1 = acc[mi][nj][half * 2 + 1] + bias[e + 1];
                if (MODE == 0) {
                    int rcol = e - which * DMODEL;
                    int h  = rcol >> 6;
                    int d0 = rcol & 63;
                    float* dst = &dstM[(((size_t)b_ * NHEAD + h) * NTOK + n_) * HD + d0];
                    dst[0] = v0; dst[1] = v1;
                } else {
                    float* dst = &C[(size_t)row * DMODEL + e];
                    dst[0] = v0; dst[1] = v1;
                }
            }
        }
    }
}

// ---------------------------------------------------------------------------
// Flash-style attention (fp32 SIMT). grid=(B*H, 11), 256 threads.
// ---------------------------------------------------------------------------
#define QT 32
#define KC 32

__global__ void __launch_bounds__(256)
attn_kernel()
{
    const int bh = blockIdx.x;
    const int qt = blockIdx.y;
    const int b  = bh / NHEAD;
    const int h  = bh - b * NHEAD;

    const float* Qg = g_Q + (size_t)bh * NTOK * HD;
    const float* Kg = g_K + (size_t)bh * NTOK * HD;
    const float* Vg = g_V + (size_t)bh * NTOK * HD;

    const int r0 = qt * QT;
    const int t  = threadIdx.x;

    __shared__ float Qs[QT][HD];
    __shared__ float Ks[KC][HD + 1];
    __shared__ float Vs[KC][HD];
    __shared__ float Ss[QT][KC + 1];
    __shared__ float sm[QT], sl[QT], sal[QT];

    for (int i = t; i < QT * (HD / 4); i += 256) {
        int row = i >> 4;
        int c4  = i & 15;
        float4 v = make_float4(0.f, 0.f, 0.f, 0.f);
        if (r0 + row < NTOK)
            v = *(const float4*)&Qg[(size_t)(r0 + row) * HD + c4 * 4];
        *(float4*)&Qs[row][c4 * 4] = v;
    }
    if (t < QT) { sm[t] = NEG_INF; sl[t] = 0.0f; }

    float o[8];
#pragma unroll
    for (int i = 0; i < 8; i++) o[i] = 0.0f;
    const int qr_o = t >> 3;
    const int db   = (t & 7) * 8;

    int lastRow = min(r0 + QT - 1, NTOK - 1);
    int Lmax = rowlimit(lastRow);
    if (r0 == 0) Lmax = NTOK;
    const int nchunks = (Lmax + KC - 1) / KC;

    const int kc2 = (t & 15) << 1;
    const int qr2 = (t >> 4) << 1;
    const int rowA = r0 + qr2;
    const int rowB = rowA + 1;
    const int La = rowlimit(min(rowA, NTOK - 1));
    const int Lb = rowlimit(min(rowB, NTOK - 1));
    const float sc = 0.125f;

    for (int ch = 0; ch < nchunks; ch++) {
        const int k0 = ch * KC;
        __syncthreads();

        for (int i = t; i < KC * (HD / 4); i += 256) {
            int row = i >> 4;
            int c4  = i & 15;
            int kg  = k0 + row;
            float4 kv = make_float4(0.f, 0.f, 0.f, 0.f);
            float4 vv = make_float4(0.f, 0.f, 0.f, 0.f);
            if (kg < NTOK) {
                kv = *(const float4*)&Kg[(size_t)kg * HD + c4 * 4];
                vv = *(const float4*)&Vg[(size_t)kg * HD + c4 * 4];
            }
            Ks[row][c4 * 4 + 0] = kv.x;
            Ks[row][c4 * 4 + 1] = kv.y;
            Ks[row][c4 * 4 + 2] = kv.z;
            Ks[row][c4 * 4 + 3] = kv.w;
            *(float4*)&Vs[row][c4 * 4] = vv;
        }
        __syncthreads();

        float s00 = 0.f, s01 = 0.f, s10 = 0.f, s11 = 0.f;
#pragma unroll
        for (int d = 0; d < HD; d++) {
            float ka = Ks[kc2][d];
            float kb = Ks[kc2 + 1][d];
            float qa = Qs[qr2][d];
            float qb = Qs[qr2 + 1][d];
            s00 += qa * ka; s01 += qa * kb;
            s10 += qb * ka; s11 += qb * kb;
        }
        int ka_g = k0 + kc2, kb_g = k0 + kc2 + 1;
        Ss[qr2][kc2]         = (ka_g < La) ? s00 * sc : NEG_INF;
        Ss[qr2][kc2 + 1]     = (kb_g < La) ? s01 * sc : NEG_INF;
        Ss[qr2 + 1][kc2]     = (ka_g < Lb) ? s10 * sc : NEG_INF;
        Ss[qr2 + 1][kc2 + 1] = (kb_g < Lb) ? s11 * sc : NEG_INF;
        __syncthreads();

        if (t < QT) {
            float mo = sm[t];
            float cm = NEG_INF;
#pragma unroll
            for (int kc = 0; kc < KC; kc++) cm = fmaxf(cm, Ss[t][kc]);
            float mn = fmaxf(mo, cm);
            float a  = __expf(mo - mn);
            float sum = 0.f;
#pragma unroll
            for (int kc = 0; kc < KC; kc++) {
                float p = __expf(Ss[t][kc] - mn);
                Ss[t][kc] = p;
                sum += p;
            }
            sm[t]  = mn;
            sl[t]  = sl[t] * a + sum;
            sal[t] = a;
        }
        __syncthreads();

        float a = sal[qr_o];
#pragma unroll
        for (int i = 0; i < 8; i++) o[i] *= a;
#pragma unroll
        for (int kc = 0; kc < KC; kc++) {
            float p = Ss[qr_o][kc];
            float4 v0 = *(float4*)&Vs[kc][db];
            float4 v1 = *(float4*)&Vs[kc][db + 4];
            o[0] += p * v0.x; o[1] += p * v0.y;
            o[2] += p * v0.z; o[3] += p * v0.w;
            o[4] += p * v1.x; o[5] += p * v1.y;
            o[6] += p * v1.z; o[7] += p * v1.w;
        }
    }

    const int n = r0 + qr_o;
    if (n < NTOK) {
        float inv = 1.0f / sl[qr_o];
        float* dst = g_AO + (size_t)(b * NTOK + n) * DMODEL + h * HD + db;
#pragma unroll
        for (int i = 0; i < 8; i++) dst[i] = o[i] * inv;
    }
}

// ---------------------------------------------------------------------------
extern "C" void kernel_launch(void* const* d_in, const int* in_sizes, int n_in,
                              void* d_out, int out_size)
{
    const float* x      = (const float*)d_in[0];
    const float* qkv_w  = (const float*)d_in[1];
    const float* qkv_b  = (const float*)d_in[2];
    const float* proj_w = (const float*)d_in[3];
    const float* proj_b = (const float*)d_in[4];
    float* out = (float*)d_out;

    (void)in_sizes; (void)n_in; (void)out_size;

    // 1) QKV GEMM (tf32 mma.sync) + scatter to Q/K/V
    {
        dim3 grid(QKVC / 128, (ROWS + 127) / 128);   // 18 x 171
        gemm_mma<0><<<grid, 128>>>(x, qkv_w, qkv_b, nullptr, ROWS);
    }
    // 2) Attention -> g_AO
    {
        dim3 grid(BATCH * NHEAD, (NTOK + QT - 1) / QT);  // 768 x 11
        attn_kernel<<<grid, 256>>>();
    }
    // 3) Output projection (tf32 mma.sync)
    {
        dim3 grid(DMODEL / 128, (ROWS + 127) / 128); // 6 x 171
        gemm_mma<1><<<grid, 128>>>(nullptr, proj_w, proj_b, out, ROWS);
    }
}